// round 5
// baseline (speedup 1.0000x reference)
#include <cuda_runtime.h>
#include <math.h>
#include <stdint.h>

#define BATCH   2
#define SEQLEN  1024
#define DMODEL  1024
#define DINNER  2048
#define NSTATE  16
#define BL      (BATCH*SEQLEN)      // 2048 rows
#define XPROJ_ROWS 33               // 1 dt + 16 B + 16 C

// ---------------- scratch (no allocs allowed) ----------------
__device__ float g_xz[(size_t)BL * 2 * DINNER];   // [bl][4096]
__device__ float g_xc[(size_t)BL * DINNER];
__device__ float g_xp[(size_t)BL * XPROJ_ROWS];
__device__ float g_dt[(size_t)BL * DINNER];
__device__ float g_yg[(size_t)BL * DINNER];
// TF32-rounded copies of GEMM inputs
__device__ float g_xr[(size_t)BL * DMODEL];         // 8 MB
__device__ float g_w1r[(size_t)(2*DINNER) * DMODEL];// 16 MB
__device__ float g_w2r[(size_t)DMODEL * DINNER];    // 8 MB

__device__ __forceinline__ unsigned f2tf32(float x) {
    unsigned r;
    asm("cvt.rna.tf32.f32 %0, %1;" : "=r"(r) : "f"(x));
    return r;
}

// ---------------- RNA pre-rounding pass ----------------
__global__ __launch_bounds__(256) void rna_round_kernel(const float* __restrict__ in,
                                                        float* __restrict__ out, int n4) {
    int i = blockIdx.x * 256 + threadIdx.x;
    if (i >= n4) return;
    float4 v = ((const float4*)in)[i];
    v.x = __uint_as_float(f2tf32(v.x));
    v.y = __uint_as_float(f2tf32(v.y));
    v.z = __uint_as_float(f2tf32(v.z));
    v.w = __uint_as_float(f2tf32(v.w));
    ((float4*)out)[i] = v;
}

// ================= TF32 mma.sync GEMM, cp.async 4-stage =================
// C[M,N] = A[M,K]*B[N,K]^T, inputs already TF32-rounded fp32.
// M%128==0, N%128==0, K%16==0.
#define BK      16
#define KPITCH  20                       // floats per smem row (16 data + 4 pad)
#define ATILE   (128 * KPITCH)           // floats per matrix per stage
#define STAGE_F (2 * ATILE)              // A + B
#define STAGES  4
#define GSMEM   (STAGES * STAGE_F * 4)   // 81920 B

__device__ __forceinline__ uint32_t smem_u32(const void* p) {
    uint32_t a;
    asm("{ .reg .u64 t; cvta.to.shared.u64 t, %1; cvt.u32.u64 %0, t; }" : "=r"(a) : "l"(p));
    return a;
}
__device__ __forceinline__ void cp_async16(uint32_t dst, const void* src) {
    asm volatile("cp.async.cg.shared.global [%0], [%1], 16;" :: "r"(dst), "l"(src));
}
__device__ __forceinline__ void cp_commit() {
    asm volatile("cp.async.commit_group;");
}
template <int N>
__device__ __forceinline__ void cp_wait() {
    asm volatile("cp.async.wait_group %0;" :: "n"(N));
}
__device__ __forceinline__ void mma_tf32(float* c, const unsigned* a, const unsigned* b) {
    asm volatile(
        "mma.sync.aligned.m16n8k8.row.col.f32.tf32.tf32.f32 "
        "{%0,%1,%2,%3}, {%4,%5,%6,%7}, {%8,%9}, {%0,%1,%2,%3};\n"
        : "+f"(c[0]), "+f"(c[1]), "+f"(c[2]), "+f"(c[3])
        : "r"(a[0]), "r"(a[1]), "r"(a[2]), "r"(a[3]), "r"(b[0]), "r"(b[1]));
}

__global__ __launch_bounds__(256, 2) void gemm_tf32_pipe(const float* __restrict__ A,
                                                         const float* __restrict__ B,
                                                         float* __restrict__ C,
                                                         int M, int N, int K) {
    extern __shared__ float smem[];
    const uint32_t smem_base = smem_u32(smem);

    const int t    = threadIdx.x;
    const int lane = t & 31;
    const int warp = t >> 5;
    const int g    = lane >> 2;          // 0..7
    const int tk   = lane & 3;           // 0..3
    const int wm   = (warp >> 2) * 64;   // 0 / 64
    const int wn   = (warp & 3) * 32;    // 0 / 32 / 64 / 96

    const int rowBase = blockIdx.y * 128;
    const int colBase = blockIdx.x * 128;
    const float* Ag = A + (size_t)rowBase * K;
    const float* Bg = B + (size_t)colBase * K;

    // loader: 2 reps x (row = id>>2 in 0..63 / 64..127, chunk = id&3)
    const int lrow0 = t >> 2;            // 0..63
    const int lch   = (t & 3) * 4;       // float offset 0,4,8,12

    const int NKT = K / BK;

    float acc[16][4];
#pragma unroll
    for (int i = 0; i < 16; i++)
#pragma unroll
        for (int j = 0; j < 4; j++) acc[i][j] = 0.f;

    // ---- load one stage ----
    auto load_stage = [&](int s, int kt) {
        const int koff = kt * BK;
        const uint32_t As = smem_base + (uint32_t)(s * STAGE_F) * 4u;
        const uint32_t Bs = As + (uint32_t)ATILE * 4u;
#pragma unroll
        for (int rep = 0; rep < 2; rep++) {
            const int row = lrow0 + rep * 64;
            const uint32_t doff = (uint32_t)(row * KPITCH + lch) * 4u;
            cp_async16(As + doff, Ag + (size_t)row * K + koff + lch);
            cp_async16(Bs + doff, Bg + (size_t)row * K + koff + lch);
        }
    };

    // prologue: stages 0..STAGES-2
#pragma unroll
    for (int s = 0; s < STAGES - 1; s++) {
        if (s < NKT) load_stage(s, s);
        cp_commit();
    }

    for (int kt = 0; kt < NKT; kt++) {
        cp_wait<STAGES - 2>();
        __syncthreads();

        // issue loads for stage kt+STAGES-1
        if (kt + STAGES - 1 < NKT) load_stage((kt + STAGES - 1) & (STAGES - 1), kt + STAGES - 1);
        cp_commit();

        const float* As = smem + (kt & (STAGES - 1)) * STAGE_F;
        const float* Bs = As + ATILE;

#pragma unroll
        for (int ks = 0; ks < 2; ks++) {
            const int k0 = ks * 8;
            unsigned a[4][4], b[4][2];
#pragma unroll
            for (int i = 0; i < 4; i++) {
                const int m0 = wm + i * 16;
                a[i][0] = __float_as_uint(As[(m0 + g)     * KPITCH + k0 + tk]);
                a[i][1] = __float_as_uint(As[(m0 + g + 8) * KPITCH + k0 + tk]);
                a[i][2] = __float_as_uint(As[(m0 + g)     * KPITCH + k0 + tk + 4]);
                a[i][3] = __float_as_uint(As[(m0 + g + 8) * KPITCH + k0 + tk + 4]);
            }
#pragma unroll
            for (int j = 0; j < 4; j++) {
                const int n0 = wn + j * 8;
                b[j][0] = __float_as_uint(Bs[(n0 + g) * KPITCH + k0 + tk]);
                b[j][1] = __float_as_uint(Bs[(n0 + g) * KPITCH + k0 + tk + 4]);
            }
#pragma unroll
            for (int i = 0; i < 4; i++)
#pragma unroll
                for (int j = 0; j < 4; j++)
                    mma_tf32(acc[i * 4 + j], a[i], b[j]);
        }
        __syncthreads();
    }

    // epilogue
#pragma unroll
    for (int i = 0; i < 4; i++) {
#pragma unroll
        for (int j = 0; j < 4; j++) {
            const float* c = acc[i * 4 + j];
            const int row0 = rowBase + wm + i * 16 + g;
            const int col  = colBase + wn + j * 8 + tk * 2;
            *(float2*)(C + (size_t)row0 * N + col)       = make_float2(c[0], c[1]);
            *(float2*)(C + (size_t)(row0 + 8) * N + col) = make_float2(c[2], c[3]);
        }
    }
}

// ---------------- causal conv (width 4) + SiLU ----------------
__global__ __launch_bounds__(256) void conv_silu_kernel(const float* __restrict__ conv_w,
                                                        const float* __restrict__ conv_b) {
    int idx = blockIdx.x * 256 + threadIdx.x;
    if (idx >= BL * DINNER) return;
    int d  = idx & (DINNER - 1);
    int bl = idx >> 11;
    int l  = bl & (SEQLEN - 1);

    float acc = conv_b[d];
#pragma unroll
    for (int k = 0; k < 4; k++) {
        int ls = l + k - 3;
        if (ls >= 0)
            acc = fmaf(conv_w[d * 4 + k],
                       g_xz[(size_t)(bl + k - 3) * (2 * DINNER) + d], acc);
    }
    float sig = 1.f / (1.f + expf(-acc));
    g_xc[idx] = acc * sig;
}

// ---------------- x_proj: xp[bl][j] = dot(xc[bl][:], W[j][:]) ----------------
__global__ __launch_bounds__(128) void xproj_kernel(const float* __restrict__ W) {
    __shared__ float sx[4][DINNER];   // 32 KB
    const int bl0 = blockIdx.x * 4;
    for (int i = threadIdx.x; i < 4 * DINNER; i += 128)
        sx[i >> 11][i & (DINNER - 1)] = g_xc[(size_t)bl0 * DINNER + i];
    __syncthreads();

    const int warp = threadIdx.x >> 5, lane = threadIdx.x & 31;
    for (int j = warp; j < XPROJ_ROWS; j += 4) {
        const float* wr = W + (size_t)j * DINNER;
        float s0 = 0.f, s1 = 0.f, s2 = 0.f, s3 = 0.f;
        for (int i = lane; i < DINNER; i += 32) {
            float w = wr[i];
            s0 = fmaf(sx[0][i], w, s0);
            s1 = fmaf(sx[1][i], w, s1);
            s2 = fmaf(sx[2][i], w, s2);
            s3 = fmaf(sx[3][i], w, s3);
        }
#pragma unroll
        for (int o = 16; o; o >>= 1) {
            s0 += __shfl_xor_sync(0xffffffffu, s0, o);
            s1 += __shfl_xor_sync(0xffffffffu, s1, o);
            s2 += __shfl_xor_sync(0xffffffffu, s2, o);
            s3 += __shfl_xor_sync(0xffffffffu, s3, o);
        }
        if (lane == 0) {
            g_xp[(size_t)(bl0 + 0) * XPROJ_ROWS + j] = s0;
            g_xp[(size_t)(bl0 + 1) * XPROJ_ROWS + j] = s1;
            g_xp[(size_t)(bl0 + 2) * XPROJ_ROWS + j] = s2;
            g_xp[(size_t)(bl0 + 3) * XPROJ_ROWS + j] = s3;
        }
    }
}

// ---------------- dt = softplus(dt_r * w + b) ----------------
__global__ __launch_bounds__(256) void dt_kernel(const float* __restrict__ dtw,
                                                 const float* __restrict__ dtb) {
    int idx = blockIdx.x * 256 + threadIdx.x;
    if (idx >= BL * DINNER) return;
    int d  = idx & (DINNER - 1);
    int bl = idx >> 11;
    float x = fmaf(g_xp[(size_t)bl * XPROJ_ROWS], dtw[d], dtb[d]);
    float sp = fmaxf(x, 0.f) + log1pf(expf(-fabsf(x)));
    g_dt[idx] = sp;
}

// ---------------- selective scan (writes TF32-rounded yg) ----------------
__global__ __launch_bounds__(256) void scan_kernel(const float* __restrict__ A_log,
                                                   const float* __restrict__ D_param) {
    const int warp_global = blockIdx.x * 8 + (threadIdx.x >> 5);
    const int lane  = threadIdx.x & 31;
    const int group = lane >> 4;
    const int n     = lane & 15;
    const int p2 = warp_global * 2;
    const int d  = (p2 & (DINNER - 1)) + group;
    const int b  = p2 >> 11;

    const float Acoef = -expf(A_log[d * NSTATE + n]);
    const float Dp    = D_param[d];

    const float* xpb = g_xp + (size_t)b * SEQLEN * XPROJ_ROWS;
    const float* dtp = g_dt + (size_t)b * SEQLEN * DINNER + d;
    const float* xcp = g_xc + (size_t)b * SEQLEN * DINNER + d;
    const float* zp  = g_xz + (size_t)b * SEQLEN * (2 * DINNER) + DINNER + d;
    float*       ygp = g_yg + (size_t)b * SEQLEN * DINNER + d;

    float h = 0.f;
    for (int t = 0; t < SEQLEN; t++) {
        const float dtv = dtp[(size_t)t * DINNER];
        const float xcv = xcp[(size_t)t * DINNER];
        const float* xpr = xpb + (size_t)t * XPROJ_ROWS;
        const float Bv = xpr[1 + n];
        const float Cv = xpr[1 + NSTATE + n];

        const float dA = __expf(dtv * Acoef);
        h = fmaf(dA, h, dtv * xcv * Bv);

        float prod = h * Cv;
        prod += __shfl_xor_sync(0xffffffffu, prod, 8);
        prod += __shfl_xor_sync(0xffffffffu, prod, 4);
        prod += __shfl_xor_sync(0xffffffffu, prod, 2);
        prod += __shfl_xor_sync(0xffffffffu, prod, 1);

        if (n == 0) {
            float y = prod + xcv * Dp;
            float z = zp[(size_t)t * (2 * DINNER)];
            float sig = 1.f / (1.f + __expf(-z));
            ygp[(size_t)t * DINNER] = __uint_as_float(f2tf32(y * (z * sig)));
        }
    }
}

// ---------------- launch ----------------
extern "C" void kernel_launch(void* const* d_in, const int* in_sizes, int n_in,
                              void* d_out, int out_size) {
    const float* x          = (const float*)d_in[0];
    const float* in_proj_w  = (const float*)d_in[1];
    const float* conv_w     = (const float*)d_in[2];
    const float* conv_b     = (const float*)d_in[3];
    const float* x_proj_w   = (const float*)d_in[4];
    const float* dt_proj_w  = (const float*)d_in[5];
    const float* dt_proj_b  = (const float*)d_in[6];
    const float* A_log      = (const float*)d_in[7];
    const float* D_param    = (const float*)d_in[8];
    const float* out_proj_w = (const float*)d_in[9];
    float* out = (float*)d_out;

    float *xz_p = nullptr, *yg_p = nullptr, *xr_p = nullptr, *w1_p = nullptr, *w2_p = nullptr;
    cudaGetSymbolAddress((void**)&xz_p, g_xz);
    cudaGetSymbolAddress((void**)&yg_p, g_yg);
    cudaGetSymbolAddress((void**)&xr_p, g_xr);
    cudaGetSymbolAddress((void**)&w1_p, g_w1r);
    cudaGetSymbolAddress((void**)&w2_p, g_w2r);

    static int smem_set = 0;
    if (!smem_set) {
        cudaFuncSetAttribute(gemm_tf32_pipe, cudaFuncAttributeMaxDynamicSharedMemorySize, GSMEM);
        smem_set = 1;
    }

    // 0) RNA-round GEMM inputs to TF32
    {
        int n4;
        n4 = (BL * DMODEL) / 4;
        rna_round_kernel<<<(n4 + 255) / 256, 256>>>(x, xr_p, n4);
        n4 = (2 * DINNER * DMODEL) / 4;
        rna_round_kernel<<<(n4 + 255) / 256, 256>>>(in_proj_w, w1_p, n4);
        n4 = (DMODEL * DINNER) / 4;
        rna_round_kernel<<<(n4 + 255) / 256, 256>>>(out_proj_w, w2_p, n4);
    }

    // 1) xz = x @ in_proj_w^T        [2048,1024] x [4096,1024]^T
    gemm_tf32_pipe<<<dim3((2 * DINNER) / 128, BL / 128), 256, GSMEM>>>(
        xr_p, w1_p, xz_p, BL, 2 * DINNER, DMODEL);

    // 2) causal conv + silu -> xc
    conv_silu_kernel<<<(BL * DINNER + 255) / 256, 256>>>(conv_w, conv_b);

    // 3) xp = xc @ x_proj_w^T (skinny N=33)
    xproj_kernel<<<BL / 4, 128>>>(x_proj_w);

    // 4) dt = softplus(...)
    dt_kernel<<<(BL * DINNER + 255) / 256, 256>>>(dt_proj_w, dt_proj_b);

    // 5) selective scan + D skip + silu(z) gate -> yg (TF32-rounded)
    scan_kernel<<<(BATCH * DINNER / 2) / 8, 256>>>(A_log, D_param);

    // 6) out = yg @ out_proj_w^T     [2048,2048] x [1024,2048]^T
    gemm_tf32_pipe<<<dim3(DMODEL / 128, BL / 128), 256, GSMEM>>>(
        yg_p, w2_p, out, BL, DMODEL, DINNER);
}

// round 6
// speedup vs baseline: 2.0486x; 2.0486x over previous
#include <cuda_runtime.h>
#include <math.h>
#include <stdint.h>

#define BATCH   2
#define SEQLEN  1024
#define DMODEL  1024
#define DINNER  2048
#define NSTATE  16
#define BL      (BATCH*SEQLEN)      // 2048 rows
#define XPROJ_ROWS 33               // 1 dt + 16 B + 16 C

// ---------------- scratch (no allocs allowed) ----------------
__device__ float g_xz[(size_t)BL * 2 * DINNER];   // [bl][4096]
__device__ float g_xc[(size_t)BL * DINNER];       // also reused as split-K partial 0
__device__ float g_xp[(size_t)BL * XPROJ_ROWS];
__device__ float g_dt[(size_t)BL * DINNER];
__device__ float g_yg[(size_t)BL * DINNER];
// TF32-rounded copies of GEMM inputs (g_xr reused as split-K partial 1)
__device__ float g_xr[(size_t)BL * DMODEL];         // 8 MB
__device__ float g_w1r[(size_t)(2*DINNER) * DMODEL];// 16 MB
__device__ float g_w2r[(size_t)DMODEL * DINNER];    // 8 MB

__device__ __forceinline__ unsigned f2tf32(float x) {
    unsigned r;
    asm("cvt.rna.tf32.f32 %0, %1;" : "=r"(r) : "f"(x));
    return r;
}

// ---------------- RNA pre-rounding pass ----------------
__global__ __launch_bounds__(256) void rna_round_kernel(const float* __restrict__ in,
                                                        float* __restrict__ out, int n4) {
    int i = blockIdx.x * 256 + threadIdx.x;
    if (i >= n4) return;
    float4 v = ((const float4*)in)[i];
    v.x = __uint_as_float(f2tf32(v.x));
    v.y = __uint_as_float(f2tf32(v.y));
    v.z = __uint_as_float(f2tf32(v.z));
    v.w = __uint_as_float(f2tf32(v.w));
    ((float4*)out)[i] = v;
}

// ---------------- add pass for split-K ----------------
__global__ __launch_bounds__(256) void add_kernel(const float* __restrict__ p0,
                                                  const float* __restrict__ p1,
                                                  float* __restrict__ out, int n4) {
    int i = blockIdx.x * 256 + threadIdx.x;
    if (i >= n4) return;
    float4 a = ((const float4*)p0)[i];
    float4 b = ((const float4*)p1)[i];
    ((float4*)out)[i] = make_float4(a.x + b.x, a.y + b.y, a.z + b.z, a.w + b.w);
}

// ================= TF32 mma.sync GEMM, cp.async 4-stage =================
// C[M,N] = A[M,K]*B[N,K]^T, inputs already TF32-rounded fp32.
// gridDim.z selects a K-split: z covers [z*klen, (z+1)*klen), writes C0 (z=0) or C1 (z=1).
#define BK      16
#define KPITCH  20
#define ATILE   (128 * KPITCH)
#define STAGE_F (2 * ATILE)
#define STAGES  4
#define GSMEM   (STAGES * STAGE_F * 4)   // 81920 B

__device__ __forceinline__ uint32_t smem_u32(const void* p) {
    uint32_t a;
    asm("{ .reg .u64 t; cvta.to.shared.u64 t, %1; cvt.u32.u64 %0, t; }" : "=r"(a) : "l"(p));
    return a;
}
__device__ __forceinline__ void cp_async16(uint32_t dst, const void* src) {
    asm volatile("cp.async.cg.shared.global [%0], [%1], 16;" :: "r"(dst), "l"(src));
}
__device__ __forceinline__ void cp_commit() {
    asm volatile("cp.async.commit_group;");
}
template <int N>
__device__ __forceinline__ void cp_wait() {
    asm volatile("cp.async.wait_group %0;" :: "n"(N));
}
__device__ __forceinline__ void mma_tf32(float* c, const unsigned* a, const unsigned* b) {
    asm volatile(
        "mma.sync.aligned.m16n8k8.row.col.f32.tf32.tf32.f32 "
        "{%0,%1,%2,%3}, {%4,%5,%6,%7}, {%8,%9}, {%0,%1,%2,%3};\n"
        : "+f"(c[0]), "+f"(c[1]), "+f"(c[2]), "+f"(c[3])
        : "r"(a[0]), "r"(a[1]), "r"(a[2]), "r"(a[3]), "r"(b[0]), "r"(b[1]));
}

__global__ __launch_bounds__(256, 2) void gemm_tf32_pipe(const float* __restrict__ A,
                                                         const float* __restrict__ B,
                                                         float* __restrict__ C0,
                                                         float* __restrict__ C1,
                                                         int M, int N, int K, int klen) {
    extern __shared__ float smem[];
    const uint32_t smem_base = smem_u32(smem);

    const int t    = threadIdx.x;
    const int lane = t & 31;
    const int warp = t >> 5;
    const int g    = lane >> 2;
    const int tk   = lane & 3;
    const int wm   = (warp >> 2) * 64;
    const int wn   = (warp & 3) * 32;

    const int rowBase = blockIdx.y * 128;
    const int colBase = blockIdx.x * 128;
    const int kbase   = blockIdx.z * klen;
    float* C = blockIdx.z ? C1 : C0;

    const float* Ag = A + (size_t)rowBase * K + kbase;
    const float* Bg = B + (size_t)colBase * K + kbase;

    const int lrow0 = t >> 2;
    const int lch   = (t & 3) * 4;
    const int NKT   = klen / BK;

    float acc[16][4];
#pragma unroll
    for (int i = 0; i < 16; i++)
#pragma unroll
        for (int j = 0; j < 4; j++) acc[i][j] = 0.f;

    auto load_stage = [&](int s, int kt) {
        const int koff = kt * BK;
        const uint32_t As = smem_base + (uint32_t)(s * STAGE_F) * 4u;
        const uint32_t Bs = As + (uint32_t)ATILE * 4u;
#pragma unroll
        for (int rep = 0; rep < 2; rep++) {
            const int row = lrow0 + rep * 64;
            const uint32_t doff = (uint32_t)(row * KPITCH + lch) * 4u;
            cp_async16(As + doff, Ag + (size_t)row * K + koff + lch);
            cp_async16(Bs + doff, Bg + (size_t)row * K + koff + lch);
        }
    };

#pragma unroll
    for (int s = 0; s < STAGES - 1; s++) {
        if (s < NKT) load_stage(s, s);
        cp_commit();
    }

    for (int kt = 0; kt < NKT; kt++) {
        cp_wait<STAGES - 2>();
        __syncthreads();

        if (kt + STAGES - 1 < NKT) load_stage((kt + STAGES - 1) & (STAGES - 1), kt + STAGES - 1);
        cp_commit();

        const float* As = smem + (kt & (STAGES - 1)) * STAGE_F;
        const float* Bs = As + ATILE;

#pragma unroll
        for (int ks = 0; ks < 2; ks++) {
            const int k0 = ks * 8;
            unsigned a[4][4], b[4][2];
#pragma unroll
            for (int i = 0; i < 4; i++) {
                const int m0 = wm + i * 16;
                a[i][0] = __float_as_uint(As[(m0 + g)     * KPITCH + k0 + tk]);
                a[i][1] = __float_as_uint(As[(m0 + g + 8) * KPITCH + k0 + tk]);
                a[i][2] = __float_as_uint(As[(m0 + g)     * KPITCH + k0 + tk + 4]);
                a[i][3] = __float_as_uint(As[(m0 + g + 8) * KPITCH + k0 + tk + 4]);
            }
#pragma unroll
            for (int j = 0; j < 4; j++) {
                const int n0 = wn + j * 8;
                b[j][0] = __float_as_uint(Bs[(n0 + g) * KPITCH + k0 + tk]);
                b[j][1] = __float_as_uint(Bs[(n0 + g) * KPITCH + k0 + tk + 4]);
            }
#pragma unroll
            for (int i = 0; i < 4; i++)
#pragma unroll
                for (int j = 0; j < 4; j++)
                    mma_tf32(acc[i * 4 + j], a[i], b[j]);
        }
        __syncthreads();
    }

#pragma unroll
    for (int i = 0; i < 4; i++) {
#pragma unroll
        for (int j = 0; j < 4; j++) {
            const float* c = acc[i * 4 + j];
            const int row0 = rowBase + wm + i * 16 + g;
            const int col  = colBase + wn + j * 8 + tk * 2;
            *(float2*)(C + (size_t)row0 * N + col)       = make_float2(c[0], c[1]);
            *(float2*)(C + (size_t)(row0 + 8) * N + col) = make_float2(c[2], c[3]);
        }
    }
}

// ---------------- causal conv (width 4) + SiLU ----------------
__global__ __launch_bounds__(256) void conv_silu_kernel(const float* __restrict__ conv_w,
                                                        const float* __restrict__ conv_b) {
    int idx = blockIdx.x * 256 + threadIdx.x;
    if (idx >= BL * DINNER) return;
    int d  = idx & (DINNER - 1);
    int bl = idx >> 11;
    int l  = bl & (SEQLEN - 1);

    float acc = conv_b[d];
#pragma unroll
    for (int k = 0; k < 4; k++) {
        int ls = l + k - 3;
        if (ls >= 0)
            acc = fmaf(conv_w[d * 4 + k],
                       g_xz[(size_t)(bl + k - 3) * (2 * DINNER) + d], acc);
    }
    float sig = 1.f / (1.f + __expf(-acc));
    g_xc[idx] = acc * sig;
}

// ---------------- x_proj ----------------
__global__ __launch_bounds__(128) void xproj_kernel(const float* __restrict__ W) {
    __shared__ float sx[4][DINNER];
    const int bl0 = blockIdx.x * 4;
    for (int i = threadIdx.x; i < 4 * DINNER; i += 128)
        sx[i >> 11][i & (DINNER - 1)] = g_xc[(size_t)bl0 * DINNER + i];
    __syncthreads();

    const int warp = threadIdx.x >> 5, lane = threadIdx.x & 31;
    for (int j = warp; j < XPROJ_ROWS; j += 4) {
        const float* wr = W + (size_t)j * DINNER;
        float s0 = 0.f, s1 = 0.f, s2 = 0.f, s3 = 0.f;
        for (int i = lane; i < DINNER; i += 32) {
            float w = wr[i];
            s0 = fmaf(sx[0][i], w, s0);
            s1 = fmaf(sx[1][i], w, s1);
            s2 = fmaf(sx[2][i], w, s2);
            s3 = fmaf(sx[3][i], w, s3);
        }
#pragma unroll
        for (int o = 16; o; o >>= 1) {
            s0 += __shfl_xor_sync(0xffffffffu, s0, o);
            s1 += __shfl_xor_sync(0xffffffffu, s1, o);
            s2 += __shfl_xor_sync(0xffffffffu, s2, o);
            s3 += __shfl_xor_sync(0xffffffffu, s3, o);
        }
        if (lane == 0) {
            g_xp[(size_t)(bl0 + 0) * XPROJ_ROWS + j] = s0;
            g_xp[(size_t)(bl0 + 1) * XPROJ_ROWS + j] = s1;
            g_xp[(size_t)(bl0 + 2) * XPROJ_ROWS + j] = s2;
            g_xp[(size_t)(bl0 + 3) * XPROJ_ROWS + j] = s3;
        }
    }
}

// ---------------- dt = softplus(dt_r * w + b) ----------------
__global__ __launch_bounds__(256) void dt_kernel(const float* __restrict__ dtw,
                                                 const float* __restrict__ dtb) {
    int idx = blockIdx.x * 256 + threadIdx.x;
    if (idx >= BL * DINNER) return;
    int d  = idx & (DINNER - 1);
    int bl = idx >> 11;
    float x = fmaf(g_xp[(size_t)bl * XPROJ_ROWS], dtw[d], dtb[d]);
    float sp = fmaxf(x, 0.f) + __logf(1.f + __expf(-fabsf(x)));
    g_dt[idx] = sp;
}

// ---------------- selective scan, t unrolled by 8 ----------------
#define SUNR 8
__global__ __launch_bounds__(256) void scan_kernel(const float* __restrict__ A_log,
                                                   const float* __restrict__ D_param) {
    const int warp_global = blockIdx.x * 8 + (threadIdx.x >> 5);
    const int lane  = threadIdx.x & 31;
    const int group = lane >> 4;
    const int n     = lane & 15;
    const int p2 = warp_global * 2;
    const int d  = (p2 & (DINNER - 1)) + group;
    const int b  = p2 >> 11;

    const float Acoef = -expf(A_log[d * NSTATE + n]);
    const float Dp    = D_param[d];

    const float* xpb = g_xp + (size_t)b * SEQLEN * XPROJ_ROWS;
    const float* dtp = g_dt + (size_t)b * SEQLEN * DINNER + d;
    const float* xcp = g_xc + (size_t)b * SEQLEN * DINNER + d;
    const float* zp  = g_xz + (size_t)b * SEQLEN * (2 * DINNER) + DINNER + d;
    float*       ygp = g_yg + (size_t)b * SEQLEN * DINNER + d;

    float h = 0.f;
    for (int t0 = 0; t0 < SEQLEN; t0 += SUNR) {
        float dtv[SUNR], xcv[SUNR], Bv[SUNR], Cv[SUNR], zv[SUNR];
#pragma unroll
        for (int u = 0; u < SUNR; u++) {
            const int t = t0 + u;
            dtv[u] = __ldg(dtp + (size_t)t * DINNER);
            xcv[u] = __ldg(xcp + (size_t)t * DINNER);
            const float* xpr = xpb + (size_t)t * XPROJ_ROWS;
            Bv[u] = __ldg(xpr + 1 + n);
            Cv[u] = __ldg(xpr + 1 + NSTATE + n);
            zv[u] = __ldg(zp + (size_t)t * (2 * DINNER));
        }
        float y[SUNR];
#pragma unroll
        for (int u = 0; u < SUNR; u++) {
            const float dA = __expf(dtv[u] * Acoef);
            h = fmaf(dA, h, dtv[u] * xcv[u] * Bv[u]);
            y[u] = h * Cv[u];
        }
#pragma unroll
        for (int u = 0; u < SUNR; u++) {
            y[u] += __shfl_xor_sync(0xffffffffu, y[u], 8);
            y[u] += __shfl_xor_sync(0xffffffffu, y[u], 4);
            y[u] += __shfl_xor_sync(0xffffffffu, y[u], 2);
            y[u] += __shfl_xor_sync(0xffffffffu, y[u], 1);
        }
        if (n == 0) {
#pragma unroll
            for (int u = 0; u < SUNR; u++) {
                const float yy = y[u] + xcv[u] * Dp;
                const float z  = zv[u];
                const float sig = 1.f / (1.f + __expf(-z));
                ygp[(size_t)(t0 + u) * DINNER] = __uint_as_float(f2tf32(yy * (z * sig)));
            }
        }
    }
}

// ---------------- launch ----------------
extern "C" void kernel_launch(void* const* d_in, const int* in_sizes, int n_in,
                              void* d_out, int out_size) {
    const float* x          = (const float*)d_in[0];
    const float* in_proj_w  = (const float*)d_in[1];
    const float* conv_w     = (const float*)d_in[2];
    const float* conv_b     = (const float*)d_in[3];
    const float* x_proj_w   = (const float*)d_in[4];
    const float* dt_proj_w  = (const float*)d_in[5];
    const float* dt_proj_b  = (const float*)d_in[6];
    const float* A_log      = (const float*)d_in[7];
    const float* D_param    = (const float*)d_in[8];
    const float* out_proj_w = (const float*)d_in[9];
    float* out = (float*)d_out;

    float *xz_p = nullptr, *yg_p = nullptr, *xr_p = nullptr, *w1_p = nullptr,
          *w2_p = nullptr, *xc_p = nullptr;
    cudaGetSymbolAddress((void**)&xz_p, g_xz);
    cudaGetSymbolAddress((void**)&yg_p, g_yg);
    cudaGetSymbolAddress((void**)&xr_p, g_xr);
    cudaGetSymbolAddress((void**)&w1_p, g_w1r);
    cudaGetSymbolAddress((void**)&w2_p, g_w2r);
    cudaGetSymbolAddress((void**)&xc_p, g_xc);

    static int smem_set = 0;
    if (!smem_set) {
        cudaFuncSetAttribute(gemm_tf32_pipe, cudaFuncAttributeMaxDynamicSharedMemorySize, GSMEM);
        smem_set = 1;
    }

    // 0) RNA-round GEMM inputs to TF32
    {
        int n4;
        n4 = (BL * DMODEL) / 4;
        rna_round_kernel<<<(n4 + 255) / 256, 256>>>(x, xr_p, n4);
        n4 = (2 * DINNER * DMODEL) / 4;
        rna_round_kernel<<<(n4 + 255) / 256, 256>>>(in_proj_w, w1_p, n4);
        n4 = (DMODEL * DINNER) / 4;
        rna_round_kernel<<<(n4 + 255) / 256, 256>>>(out_proj_w, w2_p, n4);
    }

    // 1) xz = x @ in_proj_w^T   [2048,1024] x [4096,1024]^T (no split)
    gemm_tf32_pipe<<<dim3((2 * DINNER) / 128, BL / 128, 1), 256, GSMEM>>>(
        xr_p, w1_p, xz_p, xz_p, BL, 2 * DINNER, DMODEL, DMODEL);

    // 2) causal conv + silu -> xc
    conv_silu_kernel<<<(BL * DINNER + 255) / 256, 256>>>(conv_w, conv_b);

    // 3) xp = xc @ x_proj_w^T (skinny N=33)
    xproj_kernel<<<BL / 4, 128>>>(x_proj_w);

    // 4) dt = softplus(...)
    dt_kernel<<<(BL * DINNER + 255) / 256, 256>>>(dt_proj_w, dt_proj_b);

    // 5) selective scan + D skip + silu(z) gate -> yg (TF32-rounded)
    scan_kernel<<<(BATCH * DINNER / 2) / 8, 256>>>(A_log, D_param);

    // 6) out = yg @ out_proj_w^T, split-K=2 (partials -> g_xc, g_xr; then add)
    gemm_tf32_pipe<<<dim3(DMODEL / 128, BL / 128, 2), 256, GSMEM>>>(
        yg_p, w2_p, xc_p, xr_p, BL, DMODEL, DINNER, DINNER / 2);
    {
        int n4 = (BL * DMODEL) / 4;
        add_kernel<<<(n4 + 255) / 256, 256>>>(xc_p, xr_p, out, n4);
    }
}